// round 9
// baseline (speedup 1.0000x reference)
#include <cuda_runtime.h>
#include <cuda_fp16.h>
#include <cstdint>

#define M_DIM 4096
#define N_DIM 4096
#define K_DIM 4096

// Scratch (__device__ globals: allocation-free rule)
__device__ __half g_fqw[(size_t)N_DIM * K_DIM];   // fake-quantized W, fp16
__device__ __half g_xh [(size_t)M_DIM * K_DIM];   // x, fp16

// ---------------------------------------------------------------------------
// Fused preprocess kernel (proven round 6).
//   even blocks: Q4_K_M fake-quant of W (1 warp per 256-elem block, ALU-bound)
//   odd  blocks: x -> fp16 convert (pure streaming, DRAM-bound)
// ---------------------------------------------------------------------------
__global__ void __launch_bounds__(256)
preprocess_kernel(const float4* __restrict__ W4, const float4* __restrict__ X4)
{
    const int bid = blockIdx.x;
    if (bid & 1) {
        const size_t i = (size_t)(bid >> 1) * 256 + threadIdx.x;
        float4 a = X4[i * 2];
        float4 b = X4[i * 2 + 1];
        __half2 h[4];
        h[0] = __floats2half2_rn(a.x, a.y);
        h[1] = __floats2half2_rn(a.z, a.w);
        h[2] = __floats2half2_rn(b.x, b.y);
        h[3] = __floats2half2_rn(b.z, b.w);
        reinterpret_cast<uint4*>(g_xh)[i] = *reinterpret_cast<uint4*>(h);
        return;
    }

    const int gw   = (bid >> 1) * 8 + (threadIdx.x >> 5);
    const int lane = threadIdx.x & 31;
    const size_t b4 = (size_t)gw * 64 + lane * 2;

    float4 v0 = W4[b4];
    float4 v1 = W4[b4 + 1];

    float mn = fminf(fminf(fminf(v0.x, v0.y), fminf(v0.z, v0.w)),
                     fminf(fminf(v1.x, v1.y), fminf(v1.z, v1.w)));
    float mx = fmaxf(fmaxf(fmaxf(v0.x, v0.y), fmaxf(v0.z, v0.w)),
                     fmaxf(fmaxf(v1.x, v1.y), fmaxf(v1.z, v1.w)));
    mn = fminf(mn, __shfl_xor_sync(0xFFFFFFFFu, mn, 1));
    mn = fminf(mn, __shfl_xor_sync(0xFFFFFFFFu, mn, 2));
    mx = fmaxf(mx, __shfl_xor_sync(0xFFFFFFFFu, mx, 1));
    mx = fmaxf(mx, __shfl_xor_sync(0xFFFFFFFFu, mx, 2));
    mn = fminf(mn, 0.0f);
    mx = fmaxf(mx, 0.0f);

    float sr = __fdiv_rn(fmaxf(mx - mn, 1e-8f), 15.0f);

    float smin = sr, smax = sr;
    #pragma unroll
    for (int o = 4; o < 32; o <<= 1) {
        smin = fminf(smin, __shfl_xor_sync(0xFFFFFFFFu, smin, o));
        smax = fmaxf(smax, __shfl_xor_sync(0xFFFFFFFFu, smax, o));
    }
    const float srange = fmaxf(smax - smin, 1e-8f);
    float si = fminf(fmaxf(rintf(__fdiv_rn(sr - smin, srange) * 63.0f), 0.0f), 63.0f);
    float sq = __fdiv_rn(si, 63.0f) * srange + smin;
    float sb = fmaxf(sq, 1e-8f);
    float inv = __fdiv_rn(1.0f, sb);

    auto dq = [&](float w) -> float {
        float q = fminf(fmaxf(rintf((w - mn) * inv), 0.0f), 15.0f);
        return q * sb + mn;
    };
    __half2 h[4];
    h[0] = __floats2half2_rn(dq(v0.x), dq(v0.y));
    h[1] = __floats2half2_rn(dq(v0.z), dq(v0.w));
    h[2] = __floats2half2_rn(dq(v1.x), dq(v1.y));
    h[3] = __floats2half2_rn(dq(v1.z), dq(v1.w));
    reinterpret_cast<uint4*>(g_fqw)[(size_t)gw * 32 + lane] = *reinterpret_cast<uint4*>(h);
}

// ---------------------------------------------------------------------------
// fp16 GEMM  C[m,n] = sum_k X[m,k] * W[n,k] + bias[n]
// 128x128 CTA tile, 512 threads (warp grid 4x4, warp tile 32x32), BK=64,
// SW128 swizzle, 3-stage cp.async pipeline, single barrier per iteration,
// m16n8k16 HMMA, 2 CTAs/SM (8 warps per SMSP for latency hiding).
// ---------------------------------------------------------------------------
#define BM 128
#define BN 128
#define BK 64
#define STAGE_BYTES 32768               // 16KB A + 16KB B
#define STAGES 3
#define SMEM_TOTAL (STAGES * STAGE_BYTES)  // 98304; 2 CTAs = 192KB <= 228KB
#define NK (K_DIM / BK)                 // 64
#define SWZ(o) ((o) ^ (((o) >> 3) & 0x70))

__device__ __forceinline__ void cp16s(uint32_t s, const void* g)
{
    asm volatile("cp.async.cg.shared.global [%0], [%1], 16;" :: "r"(s), "l"(g));
}
#define LDSM_X4(r0, r1, r2, r3, a) \
    asm volatile("ldmatrix.sync.aligned.m8n8.x4.shared.b16 {%0,%1,%2,%3}, [%4];" \
                 : "=r"(r0), "=r"(r1), "=r"(r2), "=r"(r3) : "r"(a))

__global__ void __launch_bounds__(512, 2)
gemm_fp16_kernel(const float* __restrict__ bias, float* __restrict__ C)
{
    extern __shared__ char smem[];
    const uint32_t sbase = (uint32_t)__cvta_generic_to_shared(smem);

    const int tid  = threadIdx.x;
    const int warp = tid >> 5;
    const int lane = tid & 31;
    const int gid  = lane >> 2;
    const int tig  = lane & 3;

    // grid swizzle: GROUP_M=8 m-tiles per group for L2 reuse
    const int GRID_N  = N_DIM / BN;     // 32
    const int GROUP_M = 8;
    const int gsz = GROUP_M * GRID_N;   // 256
    int tile  = blockIdx.x;
    int group = tile / gsz;
    int inb   = tile - group * gsz;
    int bm    = group * GROUP_M + (inb % GROUP_M);
    int bn    = inb / GROUP_M;

    const __half* Ag = g_xh  + (size_t)bm * BM * K_DIM;
    const __half* Bg = g_fqw + (size_t)bn * BN * K_DIM;

    const int wm = (warp >> 2) * 32;    // 0..96
    const int wn = (warp & 3)  * 32;    // 0..96

    // per-thread LDSM base offsets (pre-swizzle row/col parts)
    const int a_row_base = wm + (lane & 15);
    const int a_col_base = (lane >> 4) << 4;
    const int b_row_base = wn + (lane & 7) + ((lane & 16) >> 1);
    const int b_col_base = (lane & 8) << 1;

    float acc[2][4][4];
    #pragma unroll
    for (int i = 0; i < 2; i++)
        #pragma unroll
        for (int j = 0; j < 4; j++)
            #pragma unroll
            for (int r = 0; r < 4; r++) acc[i][j][r] = 0.0f;

    auto load_stage = [&](int stg, int kofs) {
        uint32_t sa = sbase + stg * STAGE_BYTES;
        #pragma unroll
        for (int i = 0; i < 2; i++) {            // A: 1024 chunks of 16B
            int c   = tid + i * 512;
            int row = c >> 3;
            cp16s(sa + SWZ(row * 128 + (c & 7) * 16),
                  Ag + (size_t)row * K_DIM + kofs + (c & 7) * 8);
        }
        uint32_t sB = sa + 16384;
        #pragma unroll
        for (int i = 0; i < 2; i++) {            // B: 1024 chunks
            int c   = tid + i * 512;
            int row = c >> 3;
            cp16s(sB + SWZ(row * 128 + (c & 7) * 16),
                  Bg + (size_t)row * K_DIM + kofs + (c & 7) * 8);
        }
    };

    load_stage(0, 0);
    asm volatile("cp.async.commit_group;");
    load_stage(1, BK);
    asm volatile("cp.async.commit_group;");

    int stg = 0;
    for (int it = 0; it < NK; ++it) {
        asm volatile("cp.async.wait_group 1;");
        __syncthreads();
        // loads for it+2 target the stage read at it-1 (safe past the barrier)
        if (it + 2 < NK) {
            int ns = stg + 2; if (ns >= STAGES) ns -= STAGES;
            load_stage(ns, (it + 2) * BK);
        }
        asm volatile("cp.async.commit_group;");

        const uint32_t aB = sbase + stg * STAGE_BYTES;
        const uint32_t bB = aB + 16384;

        #pragma unroll
        for (int ks = 0; ks < 4; ++ks) {
            const int kb = ks * 32;
            uint32_t af[2][4], bf[4][2];
            #pragma unroll
            for (int mt = 0; mt < 2; ++mt) {
                uint32_t off = (a_row_base + mt * 16) * 128 + kb + a_col_base;
                LDSM_X4(af[mt][0], af[mt][1], af[mt][2], af[mt][3], aB + SWZ(off));
            }
            {
                uint32_t off = b_row_base * 128 + kb + b_col_base;
                uint32_t r0, r1, r2, r3;
                LDSM_X4(r0, r1, r2, r3, bB + SWZ(off));
                bf[0][0] = r0; bf[0][1] = r1;
                bf[1][0] = r2; bf[1][1] = r3;
                off = (b_row_base + 16) * 128 + kb + b_col_base;
                LDSM_X4(r0, r1, r2, r3, bB + SWZ(off));
                bf[2][0] = r0; bf[2][1] = r1;
                bf[3][0] = r2; bf[3][1] = r3;
            }
            #pragma unroll
            for (int mt = 0; mt < 2; ++mt)
                #pragma unroll
                for (int nt = 0; nt < 4; ++nt) {
                    asm volatile(
                        "mma.sync.aligned.m16n8k16.row.col.f32.f16.f16.f32 "
                        "{%0,%1,%2,%3}, {%4,%5,%6,%7}, {%8,%9}, {%0,%1,%2,%3};"
                        : "+f"(acc[mt][nt][0]), "+f"(acc[mt][nt][1]),
                          "+f"(acc[mt][nt][2]), "+f"(acc[mt][nt][3])
                        : "r"(af[mt][0]), "r"(af[mt][1]), "r"(af[mt][2]), "r"(af[mt][3]),
                          "r"(bf[nt][0]), "r"(bf[nt][1]));
                }
        }
        if (++stg >= STAGES) stg = 0;
    }

    // epilogue: bias add, fp32 stores
    #pragma unroll
    for (int nt = 0; nt < 4; ++nt) {
        int n = bn * BN + wn + nt * 8 + tig * 2;
        float b0 = bias[n], b1 = bias[n + 1];
        #pragma unroll
        for (int mt = 0; mt < 2; ++mt) {
            int m = bm * BM + wm + mt * 16 + gid;
            float2 v0 = make_float2(acc[mt][nt][0] + b0, acc[mt][nt][1] + b1);
            float2 v1 = make_float2(acc[mt][nt][2] + b0, acc[mt][nt][3] + b1);
            *reinterpret_cast<float2*>(C + (size_t)m       * N_DIM + n) = v0;
            *reinterpret_cast<float2*>(C + (size_t)(m + 8) * N_DIM + n) = v1;
        }
    }
}

// ---------------------------------------------------------------------------
extern "C" void kernel_launch(void* const* d_in, const int* in_sizes, int n_in,
                              void* d_out, int out_size)
{
    const float* x    = (const float*)d_in[0];
    const float* w    = (const float*)d_in[1];
    const float* bias = (const float*)d_in[2];
    float* out = (float*)d_out;

    // fused preprocess: 8192 dequant blocks (even) + 8192 convert blocks (odd)
    preprocess_kernel<<<16384, 256>>>((const float4*)w, (const float4*)x);

    cudaFuncSetAttribute(gemm_fp16_kernel,
                         cudaFuncAttributeMaxDynamicSharedMemorySize, SMEM_TOTAL);
    const int grid = (M_DIM / BM) * (N_DIM / BN);  // 1024
    gemm_fp16_kernel<<<grid, 512, SMEM_TOTAL>>>(bias, out);
}

// round 10
// speedup vs baseline: 1.3217x; 1.3217x over previous
#include <cuda_runtime.h>
#include <cuda.h>
#include <cuda_fp16.h>
#include <cstdint>

#define M_DIM 4096
#define N_DIM 4096
#define K_DIM 4096

// Scratch (__device__ globals: allocation-free rule)
__device__ __half g_fqw[(size_t)N_DIM * K_DIM];   // fake-quantized W, fp16
__device__ __half g_xh [(size_t)M_DIM * K_DIM];   // x, fp16

// ---------------------------------------------------------------------------
// Fused preprocess kernel (proven round 6).
// ---------------------------------------------------------------------------
__global__ void __launch_bounds__(256)
preprocess_kernel(const float4* __restrict__ W4, const float4* __restrict__ X4)
{
    const int bid = blockIdx.x;
    if (bid & 1) {
        const size_t i = (size_t)(bid >> 1) * 256 + threadIdx.x;
        float4 a = X4[i * 2];
        float4 b = X4[i * 2 + 1];
        __half2 h[4];
        h[0] = __floats2half2_rn(a.x, a.y);
        h[1] = __floats2half2_rn(a.z, a.w);
        h[2] = __floats2half2_rn(b.x, b.y);
        h[3] = __floats2half2_rn(b.z, b.w);
        reinterpret_cast<uint4*>(g_xh)[i] = *reinterpret_cast<uint4*>(h);
        return;
    }

    const int gw   = (bid >> 1) * 8 + (threadIdx.x >> 5);
    const int lane = threadIdx.x & 31;
    const size_t b4 = (size_t)gw * 64 + lane * 2;

    float4 v0 = W4[b4];
    float4 v1 = W4[b4 + 1];

    float mn = fminf(fminf(fminf(v0.x, v0.y), fminf(v0.z, v0.w)),
                     fminf(fminf(v1.x, v1.y), fminf(v1.z, v1.w)));
    float mx = fmaxf(fmaxf(fmaxf(v0.x, v0.y), fmaxf(v0.z, v0.w)),
                     fmaxf(fmaxf(v1.x, v1.y), fmaxf(v1.z, v1.w)));
    mn = fminf(mn, __shfl_xor_sync(0xFFFFFFFFu, mn, 1));
    mn = fminf(mn, __shfl_xor_sync(0xFFFFFFFFu, mn, 2));
    mx = fmaxf(mx, __shfl_xor_sync(0xFFFFFFFFu, mx, 1));
    mx = fmaxf(mx, __shfl_xor_sync(0xFFFFFFFFu, mx, 2));
    mn = fminf(mn, 0.0f);
    mx = fmaxf(mx, 0.0f);

    float sr = __fdiv_rn(fmaxf(mx - mn, 1e-8f), 15.0f);

    float smin = sr, smax = sr;
    #pragma unroll
    for (int o = 4; o < 32; o <<= 1) {
        smin = fminf(smin, __shfl_xor_sync(0xFFFFFFFFu, smin, o));
        smax = fmaxf(smax, __shfl_xor_sync(0xFFFFFFFFu, smax, o));
    }
    const float srange = fmaxf(smax - smin, 1e-8f);
    float si = fminf(fmaxf(rintf(__fdiv_rn(sr - smin, srange) * 63.0f), 0.0f), 63.0f);
    float sq = __fdiv_rn(si, 63.0f) * srange + smin;
    float sb = fmaxf(sq, 1e-8f);
    float inv = __fdiv_rn(1.0f, sb);

    auto dq = [&](float w) -> float {
        float q = fminf(fmaxf(rintf((w - mn) * inv), 0.0f), 15.0f);
        return q * sb + mn;
    };
    __half2 h[4];
    h[0] = __floats2half2_rn(dq(v0.x), dq(v0.y));
    h[1] = __floats2half2_rn(dq(v0.z), dq(v0.w));
    h[2] = __floats2half2_rn(dq(v1.x), dq(v1.y));
    h[3] = __floats2half2_rn(dq(v1.z), dq(v1.w));
    reinterpret_cast<uint4*>(g_fqw)[(size_t)gw * 32 + lane] = *reinterpret_cast<uint4*>(h);
}

// ---------------------------------------------------------------------------
// fp16 GEMM with TMA tile loads.
// 128x128 CTA tile, 64x32 warp tile (8 warps), BK=64, SW128, 3-stage TMA
// pipeline + mbarrier, single __syncthreads per iteration, m16n8k16 HMMA,
// 2 CTAs/SM.
// ---------------------------------------------------------------------------
#define BM 128
#define BN 128
#define BK 64
#define STAGE_BYTES 32768               // 16KB A + 16KB B
#define STAGES 3
// smem: 3 stages (96KB) + 64B barrier block
#define MBAR_BYTES 64
#define SMEM_TOTAL (STAGES * STAGE_BYTES + MBAR_BYTES)
#define NK (K_DIM / BK)                 // 64
#define SWZ(o) ((o) ^ (((o) >> 3) & 0x70))

#define LDSM_X4(r0, r1, r2, r3, a) \
    asm volatile("ldmatrix.sync.aligned.m8n8.x4.shared.b16 {%0,%1,%2,%3}, [%4];" \
                 : "=r"(r0), "=r"(r1), "=r"(r2), "=r"(r3) : "r"(a))

#define MBARRIER_INIT(addr, cnt) \
    asm volatile("mbarrier.init.shared.b64 [%0], %1;" :: "r"(addr), "r"(cnt) : "memory")
#define MBARRIER_EXPECT_TX(addr, bytes) \
    asm volatile("mbarrier.arrive.expect_tx.shared.b64 _, [%0], %1;" :: "r"(addr), "r"(bytes) : "memory")
#define MBARRIER_WAIT_PARITY(addr, par) do {                                        \
    uint32_t _m = (addr); uint32_t _p = (par); uint32_t _done;                      \
    asm volatile("{\n\t.reg .pred p;\n\t"                                           \
        "mbarrier.try_wait.parity.acquire.cta.shared::cta.b64 p, [%1], %2;\n\t"     \
        "selp.b32 %0, 1, 0, p;\n\t}" : "=r"(_done) : "r"(_m), "r"(_p) : "memory");  \
    if (!_done) {                                                                   \
        asm volatile("{\n\t.reg .pred P1;\n\t"                                      \
            "WL_%=:\n\t"                                                            \
            "mbarrier.try_wait.parity.acquire.cta.shared::cta.b64 P1, [%0], %1, 0x989680;\n\t" \
            "@P1 bra.uni WD_%=;\n\t"                                                \
            "bra.uni WL_%=;\n\t"                                                    \
            "WD_%=:\n\t}" :: "r"(_m), "r"(_p) : "memory");                          \
    }                                                                               \
} while (0)
#define TMA_LOAD_2D(sm, tmap, cx, cy, mbar) \
    asm volatile("cp.async.bulk.tensor.2d.shared::cta.global.tile.mbarrier::complete_tx::bytes " \
                 "[%0], [%1, {%2, %3}], [%4];" \
                 :: "r"(sm), "l"(tmap), "r"(cx), "r"(cy), "r"(mbar) : "memory")

__global__ void __launch_bounds__(256, 2)
gemm_fp16_kernel(const __grid_constant__ CUtensorMap tma_a,
                 const __grid_constant__ CUtensorMap tma_b,
                 const float* __restrict__ bias, float* __restrict__ C)
{
    extern __shared__ __align__(1024) char smem[];
    const uint32_t sbase = (uint32_t)__cvta_generic_to_shared(smem);
    const uint32_t mbar  = sbase + STAGES * STAGE_BYTES;   // 3 x 8B barriers

    const int tid  = threadIdx.x;
    const int warp = tid >> 5;
    const int lane = tid & 31;
    const int gid  = lane >> 2;
    const int tig  = lane & 3;

    // grid swizzle: GROUP_M=8 m-tiles per group for L2 reuse
    const int GRID_N  = N_DIM / BN;     // 32
    const int GROUP_M = 8;
    const int gsz = GROUP_M * GRID_N;   // 256
    int tile  = blockIdx.x;
    int group = tile / gsz;
    int inb   = tile - group * gsz;
    int bm    = group * GROUP_M + (inb % GROUP_M);
    int bn    = inb / GROUP_M;

    if (tid == 0) {
        #pragma unroll
        for (int s = 0; s < STAGES; s++) MBARRIER_INIT(mbar + s * 8, 1);
    }
    __syncthreads();

    // producer: issue stage s covering k-offset it*BK
    auto issue_stage = [&](int s, int it) {
        MBARRIER_EXPECT_TX(mbar + s * 8, STAGE_BYTES);
        uint32_t sa = sbase + s * STAGE_BYTES;
        TMA_LOAD_2D(sa,         &tma_a, it * BK, bm * BM, mbar + s * 8);
        TMA_LOAD_2D(sa + 16384, &tma_b, it * BK, bn * BN, mbar + s * 8);
    };

    if (tid == 0) {
        issue_stage(0, 0);
        issue_stage(1, 1);
    }

    const int wm = (warp >> 2) * 64;
    const int wn = (warp & 3)  * 32;
    const int a_row_base = wm + (lane & 15);
    const int a_col_base = (lane >> 4) << 4;
    const int b_row_base = wn + (lane & 7) + ((lane & 16) >> 1);
    const int b_col_base = (lane & 8) << 1;

    float acc[4][4][4];
    #pragma unroll
    for (int i = 0; i < 4; i++)
        #pragma unroll
        for (int j = 0; j < 4; j++)
            #pragma unroll
            for (int r = 0; r < 4; r++) acc[i][j][r] = 0.0f;

    int stg = 0, phase = 0;
    for (int it = 0; it < NK; ++it) {
        // refill the stage read at it-1 (protected by end-of-iter barrier)
        if (tid == 0 && it + 2 < NK) {
            int ns = stg + 2; if (ns >= STAGES) ns -= STAGES;
            issue_stage(ns, it + 2);
        }
        MBARRIER_WAIT_PARITY(mbar + stg * 8, phase);

        const uint32_t aB = sbase + stg * STAGE_BYTES;
        const uint32_t bB = aB + 16384;

        #pragma unroll
        for (int ks = 0; ks < 4; ++ks) {
            const int kb = ks * 32;
            uint32_t af[4][4], bf[4][2];
            #pragma unroll
            for (int mt = 0; mt < 4; ++mt) {
                uint32_t off = (a_row_base + mt * 16) * 128 + kb + a_col_base;
                LDSM_X4(af[mt][0], af[mt][1], af[mt][2], af[mt][3], aB + SWZ(off));
            }
            #pragma unroll
            for (int nt2 = 0; nt2 < 2; ++nt2) {
                uint32_t off = (b_row_base + nt2 * 16) * 128 + kb + b_col_base;
                uint32_t r0, r1, r2, r3;
                LDSM_X4(r0, r1, r2, r3, bB + SWZ(off));
                bf[nt2 * 2][0]     = r0; bf[nt2 * 2][1]     = r1;
                bf[nt2 * 2 + 1][0] = r2; bf[nt2 * 2 + 1][1] = r3;
            }
            #pragma unroll
            for (int mt = 0; mt < 4; ++mt)
                #pragma unroll
                for (int nt = 0; nt < 4; ++nt) {
                    asm volatile(
                        "mma.sync.aligned.m16n8k16.row.col.f32.f16.f16.f32 "
                        "{%0,%1,%2,%3}, {%4,%5,%6,%7}, {%8,%9}, {%0,%1,%2,%3};"
                        : "+f"(acc[mt][nt][0]), "+f"(acc[mt][nt][1]),
                          "+f"(acc[mt][nt][2]), "+f"(acc[mt][nt][3])
                        : "r"(af[mt][0]), "r"(af[mt][1]), "r"(af[mt][2]), "r"(af[mt][3]),
                          "r"(bf[nt][0]), "r"(bf[nt][1]));
                }
        }
        __syncthreads();   // all warps done reading stage stg
        if (++stg >= STAGES) { stg = 0; phase ^= 1; }
    }

    // epilogue: bias add, fp32 stores
    #pragma unroll
    for (int nt = 0; nt < 4; ++nt) {
        int n = bn * BN + wn + nt * 8 + tig * 2;
        float b0 = bias[n], b1 = bias[n + 1];
        #pragma unroll
        for (int mt = 0; mt < 4; ++mt) {
            int m = bm * BM + wm + mt * 16 + gid;
            float2 v0 = make_float2(acc[mt][nt][0] + b0, acc[mt][nt][1] + b1);
            float2 v1 = make_float2(acc[mt][nt][2] + b0, acc[mt][nt][3] + b1);
            *reinterpret_cast<float2*>(C + (size_t)m       * N_DIM + n) = v0;
            *reinterpret_cast<float2*>(C + (size_t)(m + 8) * N_DIM + n) = v1;
        }
    }
}

// ---------------------------------------------------------------------------
// Host
// ---------------------------------------------------------------------------
typedef CUresult (*PFN_encodeTiled)(CUtensorMap*, CUtensorMapDataType, cuuint32_t, void*,
                                    const cuuint64_t*, const cuuint64_t*, const cuuint32_t*,
                                    const cuuint32_t*, CUtensorMapInterleave, CUtensorMapSwizzle,
                                    CUtensorMapL2promotion, CUtensorMapFloatOOBfill);

extern "C" void kernel_launch(void* const* d_in, const int* in_sizes, int n_in,
                              void* d_out, int out_size)
{
    const float* x    = (const float*)d_in[0];
    const float* w    = (const float*)d_in[1];
    const float* bias = (const float*)d_in[2];
    float* out = (float*)d_out;

    preprocess_kernel<<<16384, 256>>>((const float4*)w, (const float4*)x);

    void* pxh = nullptr; void* pfw = nullptr;
    cudaGetSymbolAddress(&pxh, g_xh);
    cudaGetSymbolAddress(&pfw, g_fqw);

    PFN_encodeTiled enc = nullptr;
    {
        cudaDriverEntryPointQueryResult qr;
#if CUDART_VERSION >= 12050
        cudaGetDriverEntryPointByVersion("cuTensorMapEncodeTiled", (void**)&enc, 12000,
                                         cudaEnableDefault, &qr);
#else
        cudaGetDriverEntryPoint("cuTensorMapEncodeTiled", (void**)&enc, cudaEnableDefault, &qr);
#endif
    }

    alignas(64) CUtensorMap ta, tb;
    cuuint64_t dims[2]    = {K_DIM, M_DIM};          // inner = K halves
    cuuint64_t strides[1] = {K_DIM * 2};             // row pitch bytes
    cuuint32_t es[2]      = {1, 1};
    cuuint32_t box[2]     = {BK, BM};                // 64 halves (128B) x 128 rows

    enc(&ta, CU_TENSOR_MAP_DATA_TYPE_FLOAT16, 2, pxh, dims, strides, box, es,
        CU_TENSOR_MAP_INTERLEAVE_NONE, CU_TENSOR_MAP_SWIZZLE_128B,
        CU_TENSOR_MAP_L2_PROMOTION_L2_128B, CU_TENSOR_MAP_FLOAT_OOB_FILL_NONE);
    enc(&tb, CU_TENSOR_MAP_DATA_TYPE_FLOAT16, 2, pfw, dims, strides, box, es,
        CU_TENSOR_MAP_INTERLEAVE_NONE, CU_TENSOR_MAP_SWIZZLE_128B,
        CU_TENSOR_MAP_L2_PROMOTION_L2_128B, CU_TENSOR_MAP_FLOAT_OOB_FILL_NONE);

    cudaFuncSetAttribute(gemm_fp16_kernel,
                         cudaFuncAttributeMaxDynamicSharedMemorySize, SMEM_TOTAL);
    const int grid = (M_DIM / BM) * (N_DIM / BN);  // 1024
    gemm_fp16_kernel<<<grid, 256, SMEM_TOTAL>>>(ta, tb, bias, out);
}